// round 2
// baseline (speedup 1.0000x reference)
#include <cuda_runtime.h>
#include <cuda_bf16.h>
#include <cstdint>

// ============================================================================
// Problem constants
// ============================================================================
#define BB       512
#define TT       100
#define NPRE     256
#define NPOST    256
#define KTOT     (BB * TT)        // 51200
#define KTILE    64
#define NTILES   (KTOT / KTILE)   // 800
#define KSPLIT   37               // grid (37,2,2) = 148 CTAs = exactly one wave

// smem tile: 128 rows x 64 bf16, padded to 72 bf16 (144B) per row
#define ROW_STRIDE_B 144
#define TILE_BYTES   (128 * ROW_STRIDE_B)   // 18432
#define GEMM_SMEM    (4 * TILE_BYTES)       // A0,A1,B0,B1 = 73728

// ============================================================================
// PTX helpers (baseline-PTX only: cp.async / ldmatrix / mma.sync — no tcgen05)
// ============================================================================
__device__ __forceinline__ uint32_t smem_to_u32(const void* smem_ptr) {
    uint32_t addr;
    asm("{ .reg .u64 tmp; cvta.to.shared.u64 tmp, %1; cvt.u32.u64 %0, tmp; }"
        : "=r"(addr) : "l"(smem_ptr));
    return addr;
}

__device__ __forceinline__ void cp_async_16(uint32_t dst_smem, const void* src) {
    asm volatile("cp.async.cg.shared.global [%0], [%1], 16;"
                 :: "r"(dst_smem), "l"(src) : "memory");
}
#define CP_ASYNC_COMMIT() asm volatile("cp.async.commit_group;" ::: "memory")
#define CP_ASYNC_WAIT(N)  asm volatile("cp.async.wait_group %0;" :: "n"(N) : "memory")

__device__ __forceinline__ void ldmatrix_x4(uint32_t* r, uint32_t addr) {
    asm volatile("ldmatrix.sync.aligned.m8n8.x4.shared.b16 {%0,%1,%2,%3}, [%4];"
                 : "=r"(r[0]), "=r"(r[1]), "=r"(r[2]), "=r"(r[3]) : "r"(addr));
}
__device__ __forceinline__ void ldmatrix_x2(uint32_t* r, uint32_t addr) {
    asm volatile("ldmatrix.sync.aligned.m8n8.x2.shared.b16 {%0,%1}, [%2];"
                 : "=r"(r[0]), "=r"(r[1]) : "r"(addr));
}

__device__ __forceinline__ void mma_16816(float* c, const uint32_t* a, const uint32_t* b) {
    asm volatile(
        "mma.sync.aligned.m16n8k16.row.col.f32.bf16.bf16.f32 "
        "{%0,%1,%2,%3}, {%4,%5,%6,%7}, {%8,%9}, {%0,%1,%2,%3};"
        : "+f"(c[0]), "+f"(c[1]), "+f"(c[2]), "+f"(c[3])
        : "r"(a[0]), "r"(a[1]), "r"(a[2]), "r"(a[3]), "r"(b[0]), "r"(b[1]));
}

// ============================================================================
// Scratch (device globals — sanctioned no-alloc workaround)
// ============================================================================
__device__ __nv_bfloat16 g_trace[(size_t)NPRE * KTOT];                 // [p][k] bf16
__device__ __nv_bfloat16 g_post [(size_t)NPOST * KTOT];                // [q][k] bf16
__device__ float         g_partials[(size_t)KSPLIT * NPRE * NPOST];    // 9.7 MB

// ============================================================================
// Kernel 1: exponential pre-trace + transpose to [p][k] bf16
//   grid = 512 (one CTA per batch b), 256 threads (one per p)
// ============================================================================
__global__ void stdp_trace_kernel(const float* __restrict__ pre) {
    __shared__ __nv_bfloat16 tile[256 * 54];
    const int b = blockIdx.x;
    const int p = threadIdx.x;
    const float d = 0.95122942450071403f;  // exp(-1/20)

    const float* src = pre + (size_t)b * (TT * NPRE) + p;
    float carry = 0.0f;

    const int wid  = threadIdx.x >> 5;
    const int lane = threadIdx.x & 31;

    #pragma unroll
    for (int half = 0; half < 2; ++half) {
        const int t0 = half * 50;
        #pragma unroll
        for (int tt = 0; tt < 50; ++tt) {
            float x = src[(size_t)(t0 + tt) * NPRE];
            tile[p * 54 + tt] = __float2bfloat16(carry);   // trace[t] = carry
            carry = d * (carry + x);
        }
        __syncthreads();
        if (lane < 25) {
            for (int row = wid; row < 256; row += 8) {
                uint32_t v = *(const uint32_t*)&tile[row * 54 + lane * 2];
                *(uint32_t*)((char*)(g_trace + (size_t)row * KTOT + (size_t)b * TT + t0) + lane * 4) = v;
            }
        }
        __syncthreads();
    }
}

// ============================================================================
// Kernel 2: post transpose + convert to [q][k] bf16
//   grid = 800 (k-tiles of 64), 256 threads (one per q)
// ============================================================================
__global__ void stdp_post_transpose_kernel(const float* __restrict__ post) {
    __shared__ __nv_bfloat16 tile[256 * 66];
    const int k0 = blockIdx.x * KTILE;
    const int q  = threadIdx.x;

    #pragma unroll 8
    for (int kk = 0; kk < KTILE; ++kk) {
        float v = post[(size_t)(k0 + kk) * NPOST + q];
        tile[q * 66 + kk] = __float2bfloat16(v);
    }
    __syncthreads();

    const int wid  = threadIdx.x >> 5;
    const int lane = threadIdx.x & 31;
    for (int row = wid; row < 256; row += 8) {
        uint32_t v = *(const uint32_t*)&tile[row * 66 + lane * 2];
        *(uint32_t*)((char*)(g_post + (size_t)row * KTOT + k0) + lane * 4) = v;
    }
}

// ============================================================================
// Kernel 3: split-K bf16 HMMA GEMM (mma.sync.m16n8k16), double-buffered cp.async
//   D[p,q] += sum_k trace[p,k] * post[q,k]
//   grid (KSPLIT, mtile=2, ntile=2), 256 threads = 8 warps (2 M x 4 N)
// ============================================================================
__global__ void __launch_bounds__(256, 1) stdp_gemm_kernel() {
    extern __shared__ __align__(16) char smem[];
    const uint32_t smem_u32 = smem_to_u32(smem);

    const int tid    = threadIdx.x;
    const int wid    = tid >> 5;
    const int lane   = tid & 31;
    const int kid    = blockIdx.x;
    const int mtile  = blockIdx.y;
    const int ntile  = blockIdx.z;
    const int warp_m = wid >> 2;       // 0..1  (64 rows each)
    const int warp_n = wid & 3;        // 0..3  (32 cols each)

    const __nv_bfloat16* a_base = g_trace + (size_t)(mtile * 128) * KTOT;
    const __nv_bfloat16* b_base = g_post  + (size_t)(ntile * 128) * KTOT;

    // smem offsets: A0, A1, B0, B1
    const uint32_t smA[2] = { smem_u32,                  smem_u32 + TILE_BYTES };
    const uint32_t smB[2] = { smem_u32 + 2 * TILE_BYTES, smem_u32 + 3 * TILE_BYTES };

    // per-thread cp.async coords: 1024 chunks of 16B per tile, 4 per thread
    // chunk idx = tid + it*256 ; r = idx>>3 ; c16 = idx&7
    float acc[4][4][4];
    #pragma unroll
    for (int i = 0; i < 4; ++i)
        #pragma unroll
        for (int j = 0; j < 4; ++j)
            #pragma unroll
            for (int c = 0; c < 4; ++c) acc[i][j][c] = 0.0f;

    const int n_iter = (NTILES - kid + KSPLIT - 1) / KSPLIT;   // 21 or 22

    auto issue_load = [&](int tile_idx, int buf) {
        const int k0 = (kid + tile_idx * KSPLIT) * KTILE;
        #pragma unroll
        for (int it = 0; it < 4; ++it) {
            int idx = tid + it * 256;
            int r   = idx >> 3;
            int c16 = idx & 7;
            uint32_t so = (uint32_t)(r * ROW_STRIDE_B + c16 * 16);
            cp_async_16(smA[buf] + so, a_base + (size_t)r * KTOT + k0 + c16 * 8);
            cp_async_16(smB[buf] + so, b_base + (size_t)r * KTOT + k0 + c16 * 8);
        }
        CP_ASYNC_COMMIT();
    };

    issue_load(0, 0);

    // ldmatrix lane addressing (within warp, per fragment)
    const int a_row = (lane & 15);            // + warp_m*64 + mi*16
    const int a_colh = (lane >> 4) * 8;       // + ks*16
    const int b_row = (lane & 7);             // + warp_n*32 + ni*8
    const int b_colh = ((lane >> 3) & 1) * 8; // + ks*16

    for (int i = 0; i < n_iter; ++i) {
        const int buf = i & 1;
        if (i + 1 < n_iter) {
            issue_load(i + 1, buf ^ 1);
            CP_ASYNC_WAIT(1);
        } else {
            CP_ASYNC_WAIT(0);
        }
        __syncthreads();

        #pragma unroll
        for (int ks = 0; ks < 4; ++ks) {
            uint32_t afrag[4][4];
            uint32_t bfrag[4][2];
            #pragma unroll
            for (int mi = 0; mi < 4; ++mi) {
                uint32_t addr = smA[buf]
                    + (uint32_t)((warp_m * 64 + mi * 16 + a_row) * ROW_STRIDE_B
                                 + (a_colh + ks * 16) * 2);
                ldmatrix_x4(afrag[mi], addr);
            }
            #pragma unroll
            for (int ni = 0; ni < 4; ++ni) {
                uint32_t addr = smB[buf]
                    + (uint32_t)((warp_n * 32 + ni * 8 + b_row) * ROW_STRIDE_B
                                 + (b_colh + ks * 16) * 2);
                ldmatrix_x2(bfrag[ni], addr);
            }
            #pragma unroll
            for (int mi = 0; mi < 4; ++mi)
                #pragma unroll
                for (int ni = 0; ni < 4; ++ni)
                    mma_16816(acc[mi][ni], afrag[mi], bfrag[ni]);
        }
        __syncthreads();
    }

    // ---- epilogue: write fp32 partials ----
    // mma D frag: c0,c1 -> row lane/4,  cols (lane%4)*2, +1 ; c2,c3 -> row+8
    float* part = g_partials + (size_t)kid * (NPRE * NPOST);
    const int p_base = mtile * 128 + warp_m * 64;
    const int q_base = ntile * 128 + warp_n * 32;
    #pragma unroll
    for (int mi = 0; mi < 4; ++mi) {
        #pragma unroll
        for (int ni = 0; ni < 4; ++ni) {
            int p0 = p_base + mi * 16 + (lane >> 2);
            int q  = q_base + ni * 8 + (lane & 3) * 2;
            float2 v0 = make_float2(acc[mi][ni][0], acc[mi][ni][1]);
            float2 v1 = make_float2(acc[mi][ni][2], acc[mi][ni][3]);
            *(float2*)(part + (size_t)p0 * NPOST + q)       = v0;
            *(float2*)(part + (size_t)(p0 + 8) * NPOST + q) = v1;
        }
    }
}

// ============================================================================
// Kernel 4: reduce partials + scale
// ============================================================================
__global__ void stdp_reduce_kernel(float* __restrict__ out) {
    const int idx = blockIdx.x * blockDim.x + threadIdx.x;   // 0..65535
    const float scale = (0.005f - 0.00525f) / (float)KTOT;
    float s = 0.0f;
    #pragma unroll
    for (int k = 0; k < KSPLIT; ++k)
        s += g_partials[(size_t)k * (NPRE * NPOST) + idx];
    out[idx] = s * scale;
}

// ============================================================================
// Launch
// ============================================================================
extern "C" void kernel_launch(void* const* d_in, const int* in_sizes, int n_in,
                              void* d_out, int out_size) {
    (void)in_sizes; (void)n_in; (void)out_size;
    const float* pre  = (const float*)d_in[0];
    const float* post = (const float*)d_in[1];
    float* out = (float*)d_out;

    cudaFuncSetAttribute(stdp_gemm_kernel,
                         cudaFuncAttributeMaxDynamicSharedMemorySize, GEMM_SMEM);

    stdp_trace_kernel<<<BB, 256>>>(pre);
    stdp_post_transpose_kernel<<<NTILES, 256>>>(post);
    stdp_gemm_kernel<<<dim3(KSPLIT, 2, 2), 256, GEMM_SMEM>>>();
    stdp_reduce_kernel<<<64, 1024>>>(out);
}